// round 13
// baseline (speedup 1.0000x reference)
#include <cuda_runtime.h>
#include <cuda_bf16.h>
#include <cstdint>

// SegmentMM: out[i] = A[i] @ B_eff[segA[i]]
// A:[131072,64] f32, B:[128,64,64] f32, segA int32 sorted, segB int32 perm.
// bf16 3-split (Ah*Bh + Ah*Bl + Al*Bh) on HMMA m16n8k16.
// R13: barrier-free steady state. Warp-private A staging (raw f32 cp.async,
// per-warp double buffer, per-thread wait_group), B fragments register-
// resident per segment, B smem reloaded only on segment change (CTA-uniform
// barrier path). 128 thr, 4 warps (16r x 32c each), 8x32-row tiles per CTA.

#define S_SEG 128
#define TILES 8

__device__ __align__(16) unsigned char d_Bh[S_SEG * 8192];
__device__ __align__(16) unsigned char d_Bl[S_SEG * 8192];

__device__ __forceinline__ uint32_t sw128(uint32_t off) {
    return off ^ ((off >> 3) & 0x70);
}

__device__ __forceinline__ void cvt_split4(float4 v, uint2& hi, uint2& lo) {
    __nv_bfloat162 h01 = __floats2bfloat162_rn(v.x, v.y);
    __nv_bfloat162 h23 = __floats2bfloat162_rn(v.z, v.w);
    float rx = v.x - __bfloat162float(h01.x);
    float ry = v.y - __bfloat162float(h01.y);
    float rz = v.z - __bfloat162float(h23.x);
    float rw = v.w - __bfloat162float(h23.y);
    __nv_bfloat162 l01 = __floats2bfloat162_rn(rx, ry);
    __nv_bfloat162 l23 = __floats2bfloat162_rn(rz, rw);
    hi = make_uint2(*(uint32_t*)&h01, *(uint32_t*)&h23);
    lo = make_uint2(*(uint32_t*)&l01, *(uint32_t*)&l23);
}

__device__ __forceinline__ void cvt_split2(float2 v, uint32_t& hi, uint32_t& lo) {
    __nv_bfloat162 h = __floats2bfloat162_rn(v.x, v.y);
    float rx = v.x - __bfloat162float(h.x);
    float ry = v.y - __bfloat162float(h.y);
    __nv_bfloat162 l = __floats2bfloat162_rn(rx, ry);
    hi = *(uint32_t*)&h;
    lo = *(uint32_t*)&l;
}

// ---- B pre-split kernel ----
__global__ __launch_bounds__(256)
void presplit_B_kernel(const float* __restrict__ B,
                       const int* __restrict__ segB)
{
    const int j = blockIdx.x;
    const int s = segB[j];
    const int tid = threadIdx.x;
    const float4* B4 = (const float4*)(B + (size_t)j * 4096);
    unsigned char* bh = d_Bh + (size_t)s * 8192;
    unsigned char* bl = d_Bl + (size_t)s * 8192;
    #pragma unroll
    for (int it = 0; it < 4; ++it) {
        int i = it * 256 + tid;
        float4 v = B4[i];
        int k = i >> 4, mq = i & 15;
        uint32_t sw = sw128((uint32_t)(k * 128 + mq * 8));
        uint2 hi, lo;
        cvt_split4(v, hi, lo);
        *(uint2*)(bh + sw) = hi;
        *(uint2*)(bl + sw) = lo;
    }
}

// ---- main kernel smem ----
// B: Bh 8KB + Bl 8KB at 0..16384
// A: 4 warps x 2 buffers x (16 rows x 272B) = 34816B at 16384
#define SM_BH 0
#define SM_BL 8192
#define SM_A  16384
#define A_PITCH 272
#define A_BUF   4352          // 16*272
#define SMEM_TOTAL (16384 + 8 * A_BUF)

__device__ __forceinline__ uint32_t smem_u32(const void* p) {
    uint32_t a;
    asm("{ .reg .u64 t; cvta.to.shared.u64 t, %1; cvt.u32.u64 %0, t; }"
        : "=r"(a) : "l"(p));
    return a;
}
__device__ __forceinline__ void ldsm_x4t(uint32_t& r0, uint32_t& r1,
                                         uint32_t& r2, uint32_t& r3, uint32_t a) {
    asm volatile("ldmatrix.sync.aligned.m8n8.x4.trans.shared.b16 {%0,%1,%2,%3}, [%4];"
                 : "=r"(r0), "=r"(r1), "=r"(r2), "=r"(r3) : "r"(a));
}
__device__ __forceinline__ void mma16816(float* d, const uint32_t* a,
                                         uint32_t b0, uint32_t b1) {
    asm volatile(
        "mma.sync.aligned.m16n8k16.row.col.f32.bf16.bf16.f32 "
        "{%0,%1,%2,%3}, {%4,%5,%6,%7}, {%8,%9}, {%0,%1,%2,%3};"
        : "+f"(d[0]), "+f"(d[1]), "+f"(d[2]), "+f"(d[3])
        : "r"(a[0]), "r"(a[1]), "r"(a[2]), "r"(a[3]), "r"(b0), "r"(b1));
}
#define CP_ASYNC16(dst, src)                                                   \
    asm volatile("cp.async.cg.shared.global [%0], [%1], 16;"                   \
                 :: "r"(dst), "l"(src) : "memory")
#define CP_COMMIT  asm volatile("cp.async.commit_group;" ::: "memory")
#define CP_WAIT0   asm volatile("cp.async.wait_group 0;" ::: "memory")
#define CP_WAIT1   asm volatile("cp.async.wait_group 1;" ::: "memory")

__device__ __forceinline__ void issue_A(uint32_t dst, const unsigned char* gA,
                                        int lane) {
    #pragma unroll
    for (int it = 0; it < 8; ++it) {
        int i = it * 32 + lane;          // 0..255 16B-chunks (16 rows x 256B)
        int r = i >> 4, c = i & 15;
        CP_ASYNC16(dst + (uint32_t)(r * A_PITCH + c * 16),
                   gA + (size_t)r * 256 + c * 16);
    }
    CP_COMMIT;
}

__device__ __forceinline__ void issue_B(uint32_t sb, int s, int tid) {
    const unsigned char* gh = d_Bh + (size_t)s * 8192;
    const unsigned char* gl = d_Bl + (size_t)s * 8192;
    #pragma unroll
    for (int it = 0; it < 4; ++it) {
        uint32_t off = (uint32_t)(it * 128 + tid) * 16;
        CP_ASYNC16(sb + SM_BH + off, gh + off);
        CP_ASYNC16(sb + SM_BL + off, gl + off);
    }
    CP_COMMIT;
}

__global__ __launch_bounds__(128, 4)
void segmm_hmma_kernel(const float* __restrict__ A,
                       const int* __restrict__ segA,
                       float* __restrict__ out)
{
    extern __shared__ __align__(128) unsigned char smem[];
    const uint32_t sb   = smem_u32(smem);
    const int tid   = threadIdx.x;
    const int w     = tid >> 5;          // 0..3
    const int lane  = tid & 31;
    const int r0    = blockIdx.x * (TILES * 32);
    const int wrow  = (w & 1) * 16;      // row group within 32-row tile
    const int whalf = (w >> 1);          // N half

    const int rA = wrow + (lane >> 2);   // row within tile
    const int rB = rA + 8;
    const int cb = (lane & 3) * 2;

    const uint32_t abuf0 = sb + SM_A + (uint32_t)w * (2 * A_BUF);
    const uint32_t abuf1 = abuf0 + A_BUF;

    const uint32_t b_row = (uint32_t)(lane & 15);
    const uint32_t b_nt  = (uint32_t)(lane >> 4);
    const uint32_t ntb   = (uint32_t)whalf * 4;

    // ---- initial issues: G0=B(s0), G1=A(0), G2=A(1) ----
    int s_smem = segA[r0];
    issue_B(sb, s_smem, tid);
    issue_A(abuf0, (const unsigned char*)(A + (size_t)(r0 + wrow) * 64), lane);
    issue_A(abuf1, (const unsigned char*)(A + (size_t)(r0 + 32 + wrow) * 64), lane);

    uint32_t bhf[4][8], blf[4][8];
    int s_cur = -1;

    #pragma unroll 1
    for (int t = 0; t < TILES; ++t) {
        const int tr0 = r0 + t * 32;

        if (t == TILES - 1) { CP_WAIT0; } else { CP_WAIT1; }
        if (t == 0) __syncthreads();     // B(s0) visible to all warps

        const uint32_t abase = (t & 1) ? abuf1 : abuf0;
        const uint32_t aA = abase + (uint32_t)(lane >> 2) * A_PITCH + (uint32_t)cb * 4;

        const int seg0 = segA[tr0 + rA];
        const int seg1 = segA[tr0 + rB];
        const int sLoT = segA[tr0];
        const int sHiT = segA[tr0 + 31];

        for (int s = sLoT; s <= sHiT; ++s) {
            if (s != s_smem) {           // CTA-uniform: reload B tile
                __syncthreads();         // all warps done reading old B
                issue_B(sb, s, tid);
                CP_WAIT0;
                __syncthreads();
                s_smem = s;
            }

            bool ok0 = (seg0 == s);
            bool ok1 = (seg1 == s);
            if (__ballot_sync(0xffffffffu, ok0 || ok1) == 0u) continue;

            if (s != s_cur) {            // refresh resident B fragments
                #pragma unroll
                for (int kk = 0; kk < 4; ++kk) {
                    uint32_t roff = ((uint32_t)(kk * 16) + b_row) * 128;
                    #pragma unroll
                    for (int ntp = 0; ntp < 2; ++ntp) {
                        uint32_t sw = sw128(roff + (ntb + (uint32_t)(ntp * 2) + b_nt) * 16);
                        ldsm_x4t(bhf[kk][ntp * 4 + 0], bhf[kk][ntp * 4 + 1],
                                 bhf[kk][ntp * 4 + 2], bhf[kk][ntp * 4 + 3],
                                 sb + SM_BH + sw);
                        ldsm_x4t(blf[kk][ntp * 4 + 0], blf[kk][ntp * 4 + 1],
                                 blf[kk][ntp * 4 + 2], blf[kk][ntp * 4 + 3],
                                 sb + SM_BL + sw);
                    }
                }
                s_cur = s;
            }

            float acc[4][4];
            #pragma unroll
            for (int nt = 0; nt < 4; ++nt)
                #pragma unroll
                for (int q = 0; q < 4; ++q) acc[nt][q] = 0.f;

            #pragma unroll
            for (int kk = 0; kk < 4; ++kk) {
                float2 v0, v1, v2, v3;
                asm volatile("ld.shared.v2.f32 {%0,%1}, [%2];"
                             : "=f"(v0.x), "=f"(v0.y) : "r"(aA + kk * 64));
                asm volatile("ld.shared.v2.f32 {%0,%1}, [%2];"
                             : "=f"(v1.x), "=f"(v1.y) : "r"(aA + kk * 64 + 8 * A_PITCH));
                asm volatile("ld.shared.v2.f32 {%0,%1}, [%2];"
                             : "=f"(v2.x), "=f"(v2.y) : "r"(aA + kk * 64 + 32));
                asm volatile("ld.shared.v2.f32 {%0,%1}, [%2];"
                             : "=f"(v3.x), "=f"(v3.y) : "r"(aA + kk * 64 + 8 * A_PITCH + 32));
                uint32_t ahf[4], alf[4];
                cvt_split2(v0, ahf[0], alf[0]);
                cvt_split2(v1, ahf[1], alf[1]);
                cvt_split2(v2, ahf[2], alf[2]);
                cvt_split2(v3, ahf[3], alf[3]);

                mma16816(acc[0], ahf, bhf[kk][0], bhf[kk][1]);
                mma16816(acc[1], ahf, bhf[kk][2], bhf[kk][3]);
                mma16816(acc[2], ahf, bhf[kk][4], bhf[kk][5]);
                mma16816(acc[3], ahf, bhf[kk][6], bhf[kk][7]);
                mma16816(acc[0], ahf, blf[kk][0], blf[kk][1]);
                mma16816(acc[1], ahf, blf[kk][2], blf[kk][3]);
                mma16816(acc[2], ahf, blf[kk][4], blf[kk][5]);
                mma16816(acc[3], ahf, blf[kk][6], blf[kk][7]);
                mma16816(acc[0], alf, bhf[kk][0], bhf[kk][1]);
                mma16816(acc[1], alf, bhf[kk][2], bhf[kk][3]);
                mma16816(acc[2], alf, bhf[kk][4], bhf[kk][5]);
                mma16816(acc[3], alf, bhf[kk][6], bhf[kk][7]);
            }

            float* o0 = out + (size_t)(tr0 + rA) * 64 + whalf * 32 + cb;
            float* o1 = out + (size_t)(tr0 + rB) * 64 + whalf * 32 + cb;
            #pragma unroll
            for (int nt = 0; nt < 4; ++nt) {
                if (ok0) *(float2*)(o0 + nt * 8) = make_float2(acc[nt][0], acc[nt][1]);
                if (ok1) *(float2*)(o1 + nt * 8) = make_float2(acc[nt][2], acc[nt][3]);
            }
        }

        // prefetch A(t+2) into this tile's (now-free) buffer
        if (t + 2 < TILES) {
            issue_A(abase,
                    (const unsigned char*)(A + (size_t)(tr0 + 64 + wrow) * 64),
                    lane);
        }
    }
}

extern "C" void kernel_launch(void* const* d_in, const int* in_sizes, int n_in,
                              void* d_out, int out_size) {
    const float* A    = (const float*)d_in[0];
    const float* B    = (const float*)d_in[1];
    const int*   segA = (const int*)d_in[2];
    const int*   segB = (const int*)d_in[3];
    float* out = (float*)d_out;

    const int N = in_sizes[0] / 64;      // 131072
    const int S = in_sizes[3];           // 128

    cudaFuncSetAttribute(segmm_hmma_kernel,
                         cudaFuncAttributeMaxDynamicSharedMemorySize, SMEM_TOTAL);

    presplit_B_kernel<<<S, 256>>>(B, segB);
    segmm_hmma_kernel<<<N / (TILES * 32), 128, SMEM_TOTAL>>>(A, segA, out);
}

// round 14
// speedup vs baseline: 1.1951x; 1.1951x over previous
#include <cuda_runtime.h>
#include <cuda_bf16.h>
#include <cstdint>

// SegmentMM: out[i] = A[i] @ B_eff[segA[i]]
// A:[131072,64] f32, B:[128,64,64] f32, segA int32 sorted, segB int32 perm.
// bf16 3-split (Ah*Bh + Ah*Bl + Al*Bh) on HMMA m16n8k16.
// R14 = R5 (best) + column-permuted B so the epilogue is contiguous float4
// STG.128 (halves store wavefronts), + B(s0) cp.async issued before A phase.

#define S_SEG 128

// Pre-split B, SW128-swizzled, COLUMN-PERMUTED tile images (by segment label).
// Permutation: global col 16p+4q+j ->
//   j=0,1 -> ntile 2p   cols 2q,2q+1   (byte unit 8p+q)
//   j=2,3 -> ntile 2p+1 cols 2q,2q+1   (byte unit 8p+q+4)
__device__ __align__(16) unsigned char d_Bh[S_SEG * 8192];
__device__ __align__(16) unsigned char d_Bl[S_SEG * 8192];

__device__ __forceinline__ uint32_t sw128(uint32_t off) {
    return off ^ ((off >> 3) & 0x70);
}

__device__ __forceinline__ void cvt_split4(float4 v, uint2& hi, uint2& lo) {
    __nv_bfloat162 h01 = __floats2bfloat162_rn(v.x, v.y);
    __nv_bfloat162 h23 = __floats2bfloat162_rn(v.z, v.w);
    float rx = v.x - __bfloat162float(h01.x);
    float ry = v.y - __bfloat162float(h01.y);
    float rz = v.z - __bfloat162float(h23.x);
    float rw = v.w - __bfloat162float(h23.y);
    __nv_bfloat162 l01 = __floats2bfloat162_rn(rx, ry);
    __nv_bfloat162 l23 = __floats2bfloat162_rn(rz, rw);
    hi = make_uint2(*(uint32_t*)&h01, *(uint32_t*)&h23);
    lo = make_uint2(*(uint32_t*)&l01, *(uint32_t*)&l23);
}

// ---- B pre-split kernel: convert + column-permute + swizzle ----
__global__ __launch_bounds__(256)
void presplit_B_kernel(const float* __restrict__ B,
                       const int* __restrict__ segB)
{
    const int j = blockIdx.x;
    const int s = segB[j];
    const int tid = threadIdx.x;
    const float4* B4 = (const float4*)(B + (size_t)j * 4096);
    unsigned char* bh = d_Bh + (size_t)s * 8192;
    unsigned char* bl = d_Bl + (size_t)s * 8192;
    #pragma unroll
    for (int it = 0; it < 4; ++it) {
        int i = it * 256 + tid;          // 0..1023 float4s
        float4 v = B4[i];
        int k = i >> 4, mq = i & 15;     // row k, cols 4mq..4mq+3
        int p = mq >> 2, q = mq & 3;
        uint32_t off0 = (uint32_t)(k * 128 + (8 * p + q) * 4);
        uint32_t off1 = off0 + 16;
        uint2 hi, lo;
        cvt_split4(v, hi, lo);
        *(uint32_t*)(bh + sw128(off0)) = hi.x;
        *(uint32_t*)(bh + sw128(off1)) = hi.y;
        *(uint32_t*)(bl + sw128(off0)) = lo.x;
        *(uint32_t*)(bl + sw128(off1)) = lo.y;
    }
}

// ---- main kernel smem: Ah/Al/Bh/Bl, each 64x64 bf16 SW128 = 8KB ----
#define SM_AH 0
#define SM_AL 8192
#define SM_BH 16384
#define SM_BL 24576
#define SMEM_TOTAL 32768

__device__ __forceinline__ uint32_t smem_u32(const void* p) {
    uint32_t a;
    asm("{ .reg .u64 t; cvta.to.shared.u64 t, %1; cvt.u32.u64 %0, t; }"
        : "=r"(a) : "l"(p));
    return a;
}
__device__ __forceinline__ void ldsm_x4(uint32_t& r0, uint32_t& r1,
                                        uint32_t& r2, uint32_t& r3, uint32_t a) {
    asm volatile("ldmatrix.sync.aligned.m8n8.x4.shared.b16 {%0,%1,%2,%3}, [%4];"
                 : "=r"(r0), "=r"(r1), "=r"(r2), "=r"(r3) : "r"(a));
}
__device__ __forceinline__ void ldsm_x4t(uint32_t& r0, uint32_t& r1,
                                         uint32_t& r2, uint32_t& r3, uint32_t a) {
    asm volatile("ldmatrix.sync.aligned.m8n8.x4.trans.shared.b16 {%0,%1,%2,%3}, [%4];"
                 : "=r"(r0), "=r"(r1), "=r"(r2), "=r"(r3) : "r"(a));
}
__device__ __forceinline__ void mma16816(float* d, const uint32_t* a,
                                         uint32_t b0, uint32_t b1) {
    asm volatile(
        "mma.sync.aligned.m16n8k16.row.col.f32.bf16.bf16.f32 "
        "{%0,%1,%2,%3}, {%4,%5,%6,%7}, {%8,%9}, {%0,%1,%2,%3};"
        : "+f"(d[0]), "+f"(d[1]), "+f"(d[2]), "+f"(d[3])
        : "r"(a[0]), "r"(a[1]), "r"(a[2]), "r"(a[3]), "r"(b0), "r"(b1));
}
#define CP_ASYNC16(dst, src)                                                   \
    asm volatile("cp.async.cg.shared.global [%0], [%1], 16;"                   \
                 :: "r"(dst), "l"(src) : "memory")
#define CP_COMMIT  asm volatile("cp.async.commit_group;" ::: "memory")
#define CP_WAIT0   asm volatile("cp.async.wait_group 0;" ::: "memory")

__global__ __launch_bounds__(128, 5)
void segmm_hmma_kernel(const float* __restrict__ A,
                       const int* __restrict__ segA,
                       float* __restrict__ out)
{
    __shared__ __align__(128) unsigned char smem[SMEM_TOTAL];
    const uint32_t sb  = smem_u32(smem);
    const int tid  = threadIdx.x;
    const int w    = tid >> 5;          // warp 0..3, rows w*16..w*16+15
    const int lane = tid & 31;
    const int r0   = blockIdx.x * 64;

    const int rA = w * 16 + (lane >> 2);
    const int rB = rA + 8;
    const int cq = (lane & 3) * 4;      // contiguous 4-col base (permuted B)
    const int segLoRow = segA[r0 + rA];
    const int segHiRow = segA[r0 + rB];
    const int s_lo = segA[r0];
    const int s_hi = segA[r0 + 63];

    // ---- issue B(s_lo) cp.async FIRST (flies under the A phase) ----
    {
        const unsigned char* gh = d_Bh + (size_t)s_lo * 8192;
        const unsigned char* gl = d_Bl + (size_t)s_lo * 8192;
        #pragma unroll
        for (int it = 0; it < 4; ++it) {
            uint32_t off = (uint32_t)(it * 128 + tid) * 16;
            CP_ASYNC16(sb + SM_BH + off, gh + off);
            CP_ASYNC16(sb + SM_BL + off, gl + off);
        }
        CP_COMMIT;
    }

    // ---- convert A tile (64x64 f32) -> Ah/Al bf16 SW128 smem ----
    {
        const float4* A4 = (const float4*)(A + (size_t)r0 * 64);
        #pragma unroll
        for (int it = 0; it < 8; ++it) {
            int i = it * 128 + tid;          // 0..1023 float4s
            float4 v = A4[i];
            int r = i >> 4, kq = i & 15;
            uint32_t sw = sw128((uint32_t)(r * 128 + kq * 8));
            uint2 hi, lo;
            cvt_split4(v, hi, lo);
            *(uint2*)(smem + SM_AH + sw) = hi;
            *(uint2*)(smem + SM_AL + sw) = lo;
        }
    }
    CP_WAIT0;
    __syncthreads();

    const uint32_t a_row = (uint32_t)(w * 16 + (lane & 15));
    const uint32_t a_sel = (uint32_t)(lane >> 4) * 16;
    const uint32_t b_row = (uint32_t)(lane & 15);
    const uint32_t b_nt  = (uint32_t)(lane >> 4);   // 0 or 1

    for (int s = s_lo; s <= s_hi; ++s) {
        if (s > s_lo) {
            __syncthreads();   // everyone done reading previous B
            const unsigned char* gh = d_Bh + (size_t)s * 8192;
            const unsigned char* gl = d_Bl + (size_t)s * 8192;
            #pragma unroll
            for (int it = 0; it < 4; ++it) {
                uint32_t off = (uint32_t)(it * 128 + tid) * 16;
                CP_ASYNC16(sb + SM_BH + off, gh + off);
                CP_ASYNC16(sb + SM_BL + off, gl + off);
            }
            CP_COMMIT;
            CP_WAIT0;
            __syncthreads();
        }

        bool okA = (segLoRow == s);
        bool okB = (segHiRow == s);
        if (__ballot_sync(0xffffffffu, okA || okB) == 0u) continue;

        float acc[8][4];
        #pragma unroll
        for (int nt = 0; nt < 8; ++nt)
            #pragma unroll
            for (int q = 0; q < 4; ++q) acc[nt][q] = 0.f;

        #pragma unroll
        for (int kk = 0; kk < 4; ++kk) {
            uint32_t asw = sw128(a_row * 128 + (uint32_t)(kk * 32) + a_sel);
            uint32_t ah[4], al[4];
            ldsm_x4(ah[0], ah[1], ah[2], ah[3], sb + SM_AH + asw);
            ldsm_x4(al[0], al[1], al[2], al[3], sb + SM_AL + asw);

            uint32_t roff = ((uint32_t)(kk * 16) + b_row) * 128;
            #pragma unroll
            for (int ntp = 0; ntp < 4; ++ntp) {
                uint32_t sw = sw128(roff + ((uint32_t)(ntp * 2) + b_nt) * 16);
                uint32_t bh0, bh1, bh2, bh3, bl0, bl1, bl2, bl3;
                ldsm_x4t(bh0, bh1, bh2, bh3, sb + SM_BH + sw);
                ldsm_x4t(bl0, bl1, bl2, bl3, sb + SM_BL + sw);
                mma16816(acc[ntp * 2],     ah, bh0, bh1);
                mma16816(acc[ntp * 2 + 1], ah, bh2, bh3);
                mma16816(acc[ntp * 2],     ah, bl0, bl1);
                mma16816(acc[ntp * 2 + 1], ah, bl2, bl3);
                mma16816(acc[ntp * 2],     al, bh0, bh1);
                mma16816(acc[ntp * 2 + 1], al, bh2, bh3);
            }
        }

        // ---- contiguous float4 epilogue (permuted cols) ----
        float* o0 = out + (size_t)(r0 + rA) * 64 + cq;
        float* o1 = out + (size_t)(r0 + rB) * 64 + cq;
        #pragma unroll
        for (int p = 0; p < 4; ++p) {
            if (okA) *(float4*)(o0 + p * 16) =
                make_float4(acc[2 * p][0], acc[2 * p][1],
                            acc[2 * p + 1][0], acc[2 * p + 1][1]);
            if (okB) *(float4*)(o1 + p * 16) =
                make_float4(acc[2 * p][2], acc[2 * p][3],
                            acc[2 * p + 1][2], acc[2 * p + 1][3]);
        }
    }
}

extern "C" void kernel_launch(void* const* d_in, const int* in_sizes, int n_in,
                              void* d_out, int out_size) {
    const float* A    = (const float*)d_in[0];
    const float* B    = (const float*)d_in[1];
    const int*   segA = (const int*)d_in[2];
    const int*   segB = (const int*)d_in[3];
    float* out = (float*)d_out;

    const int N = in_sizes[0] / 64;      // 131072
    const int S = in_sizes[3];           // 128

    presplit_B_kernel<<<S, 256>>>(B, segB);
    segmm_hmma_kernel<<<N / 64, 128>>>(A, segA, out);
}

// round 15
// speedup vs baseline: 1.3266x; 1.1100x over previous
#include <cuda_runtime.h>
#include <cuda_bf16.h>
#include <cstdint>

// SegmentMM: out[i] = A[i] @ B_eff[segA[i]]
// A:[131072,64] f32, B:[128,64,64] f32, segA int32 sorted, segB int32 perm.
// bf16 3-split (Ah*Bh + Ah*Bl + Al*Bh) on HMMA m16n8k16.
// R15 = R14 skeleton, warp tile 32 rows x 32 cols (2 mtiles x 4 ntiles):
// halves B smem re-reads per row (the dominant L1 wavefront item) while
// keeping acc at 32 regs. Permuted-B float4 epilogue retained.

#define S_SEG 128

// Pre-split B, SW128-swizzled, COLUMN-PERMUTED tile images (by segment label).
// Permutation: global col 16p+4q+j ->
//   j=0,1 -> ntile 2p   cols 2q,2q+1   (byte unit 8p+q)
//   j=2,3 -> ntile 2p+1 cols 2q,2q+1   (byte unit 8p+q+4)
__device__ __align__(16) unsigned char d_Bh[S_SEG * 8192];
__device__ __align__(16) unsigned char d_Bl[S_SEG * 8192];

__device__ __forceinline__ uint32_t sw128(uint32_t off) {
    return off ^ ((off >> 3) & 0x70);
}

__device__ __forceinline__ void cvt_split4(float4 v, uint2& hi, uint2& lo) {
    __nv_bfloat162 h01 = __floats2bfloat162_rn(v.x, v.y);
    __nv_bfloat162 h23 = __floats2bfloat162_rn(v.z, v.w);
    float rx = v.x - __bfloat162float(h01.x);
    float ry = v.y - __bfloat162float(h01.y);
    float rz = v.z - __bfloat162float(h23.x);
    float rw = v.w - __bfloat162float(h23.y);
    __nv_bfloat162 l01 = __floats2bfloat162_rn(rx, ry);
    __nv_bfloat162 l23 = __floats2bfloat162_rn(rz, rw);
    hi = make_uint2(*(uint32_t*)&h01, *(uint32_t*)&h23);
    lo = make_uint2(*(uint32_t*)&l01, *(uint32_t*)&l23);
}

// ---- B pre-split kernel: convert + column-permute + swizzle ----
__global__ __launch_bounds__(256)
void presplit_B_kernel(const float* __restrict__ B,
                       const int* __restrict__ segB)
{
    const int j = blockIdx.x;
    const int s = segB[j];
    const int tid = threadIdx.x;
    const float4* B4 = (const float4*)(B + (size_t)j * 4096);
    unsigned char* bh = d_Bh + (size_t)s * 8192;
    unsigned char* bl = d_Bl + (size_t)s * 8192;
    #pragma unroll
    for (int it = 0; it < 4; ++it) {
        int i = it * 256 + tid;          // 0..1023 float4s
        float4 v = B4[i];
        int k = i >> 4, mq = i & 15;     // row k, cols 4mq..4mq+3
        int p = mq >> 2, q = mq & 3;
        uint32_t off0 = (uint32_t)(k * 128 + (8 * p + q) * 4);
        uint32_t off1 = off0 + 16;
        uint2 hi, lo;
        cvt_split4(v, hi, lo);
        *(uint32_t*)(bh + sw128(off0)) = hi.x;
        *(uint32_t*)(bh + sw128(off1)) = hi.y;
        *(uint32_t*)(bl + sw128(off0)) = lo.x;
        *(uint32_t*)(bl + sw128(off1)) = lo.y;
    }
}

// ---- main kernel smem: Ah/Al/Bh/Bl, each 64x64 bf16 SW128 = 8KB ----
#define SM_AH 0
#define SM_AL 8192
#define SM_BH 16384
#define SM_BL 24576
#define SMEM_TOTAL 32768

__device__ __forceinline__ uint32_t smem_u32(const void* p) {
    uint32_t a;
    asm("{ .reg .u64 t; cvta.to.shared.u64 t, %1; cvt.u32.u64 %0, t; }"
        : "=r"(a) : "l"(p));
    return a;
}
__device__ __forceinline__ void ldsm_x4(uint32_t& r0, uint32_t& r1,
                                        uint32_t& r2, uint32_t& r3, uint32_t a) {
    asm volatile("ldmatrix.sync.aligned.m8n8.x4.shared.b16 {%0,%1,%2,%3}, [%4];"
                 : "=r"(r0), "=r"(r1), "=r"(r2), "=r"(r3) : "r"(a));
}
__device__ __forceinline__ void ldsm_x4t(uint32_t& r0, uint32_t& r1,
                                         uint32_t& r2, uint32_t& r3, uint32_t a) {
    asm volatile("ldmatrix.sync.aligned.m8n8.x4.trans.shared.b16 {%0,%1,%2,%3}, [%4];"
                 : "=r"(r0), "=r"(r1), "=r"(r2), "=r"(r3) : "r"(a));
}
__device__ __forceinline__ void mma16816(float* d, const uint32_t* a,
                                         uint32_t b0, uint32_t b1) {
    asm volatile(
        "mma.sync.aligned.m16n8k16.row.col.f32.bf16.bf16.f32 "
        "{%0,%1,%2,%3}, {%4,%5,%6,%7}, {%8,%9}, {%0,%1,%2,%3};"
        : "+f"(d[0]), "+f"(d[1]), "+f"(d[2]), "+f"(d[3])
        : "r"(a[0]), "r"(a[1]), "r"(a[2]), "r"(a[3]), "r"(b0), "r"(b1));
}
#define CP_ASYNC16(dst, src)                                                   \
    asm volatile("cp.async.cg.shared.global [%0], [%1], 16;"                   \
                 :: "r"(dst), "l"(src) : "memory")
#define CP_COMMIT  asm volatile("cp.async.commit_group;" ::: "memory")
#define CP_WAIT0   asm volatile("cp.async.wait_group 0;" ::: "memory")

__global__ __launch_bounds__(128, 5)
void segmm_hmma_kernel(const float* __restrict__ A,
                       const int* __restrict__ segA,
                       float* __restrict__ out)
{
    __shared__ __align__(128) unsigned char smem[SMEM_TOTAL];
    const uint32_t sb  = smem_u32(smem);
    const int tid  = threadIdx.x;
    const int w    = tid >> 5;
    const int lane = tid & 31;
    const int r0   = blockIdx.x * 64;

    // warp tile: rows wrow..wrow+31, cols whalf*32..+31
    const int wrow  = (w & 1) * 32;
    const int whalf = (w >> 1);

    const int rA = wrow + (lane >> 2);       // mtile0 rows rA, rA+8
    const int cq = (lane & 3) * 4;           // contiguous 4-col base (permuted)
    const int seg0 = segA[r0 + rA];
    const int seg1 = segA[r0 + rA + 8];
    const int seg2 = segA[r0 + rA + 16];     // mtile1 rows
    const int seg3 = segA[r0 + rA + 24];
    const int s_lo = segA[r0];
    const int s_hi = segA[r0 + 63];

    // ---- issue B(s_lo) cp.async FIRST (flies under the A phase) ----
    {
        const unsigned char* gh = d_Bh + (size_t)s_lo * 8192;
        const unsigned char* gl = d_Bl + (size_t)s_lo * 8192;
        #pragma unroll
        for (int it = 0; it < 4; ++it) {
            uint32_t off = (uint32_t)(it * 128 + tid) * 16;
            CP_ASYNC16(sb + SM_BH + off, gh + off);
            CP_ASYNC16(sb + SM_BL + off, gl + off);
        }
        CP_COMMIT;
    }

    // ---- convert A tile (64x64 f32) -> Ah/Al bf16 SW128 smem ----
    {
        const float4* A4 = (const float4*)(A + (size_t)r0 * 64);
        #pragma unroll
        for (int it = 0; it < 8; ++it) {
            int i = it * 128 + tid;          // 0..1023 float4s
            float4 v = A4[i];
            int r = i >> 4, kq = i & 15;
            uint32_t sw = sw128((uint32_t)(r * 128 + kq * 8));
            uint2 hi, lo;
            cvt_split4(v, hi, lo);
            *(uint2*)(smem + SM_AH + sw) = hi;
            *(uint2*)(smem + SM_AL + sw) = lo;
        }
    }
    CP_WAIT0;
    __syncthreads();

    const uint32_t a_row = (uint32_t)(wrow + (lane & 15));   // mtile0 ldsm row
    const uint32_t a_sel = (uint32_t)(lane >> 4) * 16;
    const uint32_t b_row = (uint32_t)(lane & 15);
    const uint32_t b_nt  = (uint32_t)(lane >> 4);            // 0 or 1

    for (int s = s_lo; s <= s_hi; ++s) {
        if (s > s_lo) {
            __syncthreads();   // everyone done reading previous B
            const unsigned char* gh = d_Bh + (size_t)s * 8192;
            const unsigned char* gl = d_Bl + (size_t)s * 8192;
            #pragma unroll
            for (int it = 0; it < 4; ++it) {
                uint32_t off = (uint32_t)(it * 128 + tid) * 16;
                CP_ASYNC16(sb + SM_BH + off, gh + off);
                CP_ASYNC16(sb + SM_BL + off, gl + off);
            }
            CP_COMMIT;
            CP_WAIT0;
            __syncthreads();
        }

        bool ok0 = (seg0 == s), ok1 = (seg1 == s);
        bool ok2 = (seg2 == s), ok3 = (seg3 == s);
        if (__ballot_sync(0xffffffffu, ok0 || ok1 || ok2 || ok3) == 0u) continue;

        float acc[2][4][4];                  // [mtile][ntile_local][frag]
        #pragma unroll
        for (int m = 0; m < 2; ++m)
            #pragma unroll
            for (int nt = 0; nt < 4; ++nt)
                #pragma unroll
                for (int q = 0; q < 4; ++q) acc[m][nt][q] = 0.f;

        #pragma unroll
        for (int kk = 0; kk < 4; ++kk) {
            // A fragments for both mtiles (sw128 commutes with +2048: bit11)
            uint32_t asw0 = sw128(a_row * 128 + (uint32_t)(kk * 32) + a_sel);
            uint32_t asw1 = asw0 + 16 * 128;
            uint32_t ah0[4], al0[4], ah1[4], al1[4];
            ldsm_x4(ah0[0], ah0[1], ah0[2], ah0[3], sb + SM_AH + asw0);
            ldsm_x4(al0[0], al0[1], al0[2], al0[3], sb + SM_AL + asw0);
            ldsm_x4(ah1[0], ah1[1], ah1[2], ah1[3], sb + SM_AH + asw1);
            ldsm_x4(al1[0], al1[1], al1[2], al1[3], sb + SM_AL + asw1);

            uint32_t roff = ((uint32_t)(kk * 16) + b_row) * 128;
            #pragma unroll
            for (int pl = 0; pl < 2; ++pl) {    // ntile-pair within half
                uint32_t cu = ((uint32_t)(whalf * 2 + pl) * 2 + b_nt) * 16;
                uint32_t sw = sw128(roff + cu);
                uint32_t bh0, bh1, bh2, bh3, bl0, bl1, bl2, bl3;
                ldsm_x4t(bh0, bh1, bh2, bh3, sb + SM_BH + sw);
                ldsm_x4t(bl0, bl1, bl2, bl3, sb + SM_BL + sw);
                // mtile0
                mma16816(acc[0][pl * 2],     ah0, bh0, bh1);
                mma16816(acc[0][pl * 2 + 1], ah0, bh2, bh3);
                mma16816(acc[0][pl * 2],     ah0, bl0, bl1);
                mma16816(acc[0][pl * 2 + 1], ah0, bl2, bl3);
                mma16816(acc[0][pl * 2],     al0, bh0, bh1);
                mma16816(acc[0][pl * 2 + 1], al0, bh2, bh3);
                // mtile1 (reuses the same B fragments)
                mma16816(acc[1][pl * 2],     ah1, bh0, bh1);
                mma16816(acc[1][pl * 2 + 1], ah1, bh2, bh3);
                mma16816(acc[1][pl * 2],     ah1, bl0, bl1);
                mma16816(acc[1][pl * 2 + 1], ah1, bl2, bl3);
                mma16816(acc[1][pl * 2],     al1, bh0, bh1);
                mma16816(acc[1][pl * 2 + 1], al1, bh2, bh3);
            }
        }

        // ---- contiguous float4 epilogue (permuted cols) ----
        #pragma unroll
        for (int m = 0; m < 2; ++m) {
            float* oA = out + (size_t)(r0 + rA + m * 16) * 64;
            float* oB = oA + (size_t)8 * 64;
            bool okAm = m ? ok2 : ok0;
            bool okBm = m ? ok3 : ok1;
            #pragma unroll
            for (int pl = 0; pl < 2; ++pl) {
                int col = 16 * (whalf * 2 + pl) + cq;
                if (okAm) *(float4*)(oA + col) =
                    make_float4(acc[m][2 * pl][0], acc[m][2 * pl][1],
                                acc[m][2 * pl + 1][0], acc[m][2 * pl + 1][1]);
                if (okBm) *(float4*)(oB + col) =
                    make_float4(acc[m][2 * pl][2], acc[m][2 * pl][3],
                                acc[m][2 * pl + 1][2], acc[m][2 * pl + 1][3]);
            }
        }
    }
}

extern "C" void kernel_launch(void* const* d_in, const int* in_sizes, int n_in,
                              void* d_out, int out_size) {
    const float* A    = (const float*)d_in[0];
    const float* B    = (const float*)d_in[1];
    const int*   segA = (const int*)d_in[2];
    const int*   segB = (const int*)d_in[3];
    float* out = (float*)d_out;

    const int N = in_sizes[0] / 64;      // 131072
    const int S = in_sizes[3];           // 128

    presplit_B_kernel<<<S, 256>>>(B, segB);
    segmm_hmma_kernel<<<N / 64, 128>>>(A, segA, out);
}

// round 16
// speedup vs baseline: 1.6610x; 1.2521x over previous
#include <cuda_runtime.h>
#include <cuda_fp16.h>
#include <cstdint>

// SegmentMM: out[i] = A[i] @ B_eff[segA[i]]
// A:[131072,64] f32, B:[128,64,64] f32, segA int32 sorted, segB int32 perm.
// R16: SINGLE-PRODUCT FP16 HMMA (m16n8k16 f32.f16.f16.f32). fp16's 11
// mantissa bits give ~2.5e-4 rel err (threshold 1e-3). Kills 2/3 of MMAs,
// half of all smem traffic and staging vs the bf16 3-split.
// Dataflow = R15 (proven): 64-row CTA, 4 warps, 32x32 warp tile, permuted-B
// contiguous float4 epilogue, B-before-A cp.async.

#define S_SEG 128

// Pre-split B: fp16, SW128-swizzled, COLUMN-PERMUTED (by segment label).
// Permutation: global col 16p+4q+j ->
//   j=0,1 -> ntile 2p   cols 2q,2q+1   (byte unit 8p+q)
//   j=2,3 -> ntile 2p+1 cols 2q,2q+1   (byte unit 8p+q+4)
__device__ __align__(16) unsigned char d_Bf[S_SEG * 8192];

__device__ __forceinline__ uint32_t sw128(uint32_t off) {
    return off ^ ((off >> 3) & 0x70);
}

__device__ __forceinline__ uint2 cvt_h4(float4 v) {
    __half2 h01 = __floats2half2_rn(v.x, v.y);
    __half2 h23 = __floats2half2_rn(v.z, v.w);
    return make_uint2(*(uint32_t*)&h01, *(uint32_t*)&h23);
}

// ---- B pre-convert kernel: fp16 + column-permute + swizzle ----
__global__ __launch_bounds__(256)
void preconv_B_kernel(const float* __restrict__ B,
                      const int* __restrict__ segB)
{
    const int j = blockIdx.x;
    const int s = segB[j];
    const int tid = threadIdx.x;
    const float4* B4 = (const float4*)(B + (size_t)j * 4096);
    unsigned char* bf = d_Bf + (size_t)s * 8192;
    #pragma unroll
    for (int it = 0; it < 4; ++it) {
        int i = it * 256 + tid;          // 0..1023 float4s
        float4 v = B4[i];
        int k = i >> 4, mq = i & 15;     // row k, cols 4mq..4mq+3
        int p = mq >> 2, q = mq & 3;
        uint32_t off0 = (uint32_t)(k * 128 + (8 * p + q) * 4);
        uint2 h = cvt_h4(v);
        *(uint32_t*)(bf + sw128(off0))      = h.x;
        *(uint32_t*)(bf + sw128(off0 + 16)) = h.y;
    }
}

// ---- main kernel smem: A fp16 8KB + B fp16 8KB ----
#define SM_A 0
#define SM_B 8192
#define SMEM_TOTAL 16384

__device__ __forceinline__ uint32_t smem_u32(const void* p) {
    uint32_t a;
    asm("{ .reg .u64 t; cvta.to.shared.u64 t, %1; cvt.u32.u64 %0, t; }"
        : "=r"(a) : "l"(p));
    return a;
}
__device__ __forceinline__ void ldsm_x4(uint32_t& r0, uint32_t& r1,
                                        uint32_t& r2, uint32_t& r3, uint32_t a) {
    asm volatile("ldmatrix.sync.aligned.m8n8.x4.shared.b16 {%0,%1,%2,%3}, [%4];"
                 : "=r"(r0), "=r"(r1), "=r"(r2), "=r"(r3) : "r"(a));
}
__device__ __forceinline__ void ldsm_x4t(uint32_t& r0, uint32_t& r1,
                                         uint32_t& r2, uint32_t& r3, uint32_t a) {
    asm volatile("ldmatrix.sync.aligned.m8n8.x4.trans.shared.b16 {%0,%1,%2,%3}, [%4];"
                 : "=r"(r0), "=r"(r1), "=r"(r2), "=r"(r3) : "r"(a));
}
__device__ __forceinline__ void mma16816(float* d, const uint32_t* a,
                                         uint32_t b0, uint32_t b1) {
    asm volatile(
        "mma.sync.aligned.m16n8k16.row.col.f32.f16.f16.f32 "
        "{%0,%1,%2,%3}, {%4,%5,%6,%7}, {%8,%9}, {%0,%1,%2,%3};"
        : "+f"(d[0]), "+f"(d[1]), "+f"(d[2]), "+f"(d[3])
        : "r"(a[0]), "r"(a[1]), "r"(a[2]), "r"(a[3]), "r"(b0), "r"(b1));
}
#define CP_ASYNC16(dst, src)                                                   \
    asm volatile("cp.async.cg.shared.global [%0], [%1], 16;"                   \
                 :: "r"(dst), "l"(src) : "memory")
#define CP_COMMIT  asm volatile("cp.async.commit_group;" ::: "memory")
#define CP_WAIT0   asm volatile("cp.async.wait_group 0;" ::: "memory")

__global__ __launch_bounds__(128, 6)
void segmm_hmma_kernel(const float* __restrict__ A,
                       const int* __restrict__ segA,
                       float* __restrict__ out)
{
    __shared__ __align__(128) unsigned char smem[SMEM_TOTAL];
    const uint32_t sb  = smem_u32(smem);
    const int tid  = threadIdx.x;
    const int w    = tid >> 5;
    const int lane = tid & 31;
    const int r0   = blockIdx.x * 64;

    // warp tile: rows wrow..wrow+31, cols whalf*32..+31
    const int wrow  = (w & 1) * 32;
    const int whalf = (w >> 1);

    const int rA = wrow + (lane >> 2);       // mtile0 rows rA, rA+8
    const int cq = (lane & 3) * 4;           // contiguous 4-col base (permuted)
    const int seg0 = segA[r0 + rA];
    const int seg1 = segA[r0 + rA + 8];
    const int seg2 = segA[r0 + rA + 16];     // mtile1 rows
    const int seg3 = segA[r0 + rA + 24];
    const int s_lo = segA[r0];
    const int s_hi = segA[r0 + 63];

    // ---- issue B(s_lo) cp.async FIRST (flies under the A phase) ----
    {
        const unsigned char* gb = d_Bf + (size_t)s_lo * 8192;
        #pragma unroll
        for (int it = 0; it < 4; ++it) {
            uint32_t off = (uint32_t)(it * 128 + tid) * 16;
            CP_ASYNC16(sb + SM_B + off, gb + off);
        }
        CP_COMMIT;
    }

    // ---- convert A tile (64x64 f32) -> fp16 SW128 smem ----
    {
        const float4* A4 = (const float4*)(A + (size_t)r0 * 64);
        #pragma unroll
        for (int it = 0; it < 8; ++it) {
            int i = it * 128 + tid;          // 0..1023 float4s
            float4 v = A4[i];
            int r = i >> 4, kq = i & 15;
            uint32_t sw = sw128((uint32_t)(r * 128 + kq * 8));
            *(uint2*)(smem + SM_A + sw) = cvt_h4(v);
        }
    }
    CP_WAIT0;
    __syncthreads();

    const uint32_t a_row = (uint32_t)(wrow + (lane & 15));   // mtile0 ldsm row
    const uint32_t a_sel = (uint32_t)(lane >> 4) * 16;
    const uint32_t b_row = (uint32_t)(lane & 15);
    const uint32_t b_nt  = (uint32_t)(lane >> 4);            // 0 or 1

    for (int s = s_lo; s <= s_hi; ++s) {
        if (s > s_lo) {
            __syncthreads();   // everyone done reading previous B
            const unsigned char* gb = d_Bf + (size_t)s * 8192;
            #pragma unroll
            for (int it = 0; it < 4; ++it) {
                uint32_t off = (uint32_t)(it * 128 + tid) * 16;
                CP_ASYNC16(sb + SM_B + off, gb + off);
            }
            CP_COMMIT;
            CP_WAIT0;
            __syncthreads();
        }

        bool ok0 = (seg0 == s), ok1 = (seg1 == s);
        bool ok2 = (seg2 == s), ok3 = (seg3 == s);
        if (__ballot_sync(0xffffffffu, ok0 || ok1 || ok2 || ok3) == 0u) continue;

        float acc[2][4][4];                  // [mtile][ntile_local][frag]
        #pragma unroll
        for (int m = 0; m < 2; ++m)
            #pragma unroll
            for (int nt = 0; nt < 4; ++nt)
                #pragma unroll
                for (int q = 0; q < 4; ++q) acc[m][nt][q] = 0.f;

        #pragma unroll
        for (int kk = 0; kk < 4; ++kk) {
            // A fragments for both mtiles (sw128 commutes with +2048: bit11)
            uint32_t asw0 = sw128(a_row * 128 + (uint32_t)(kk * 32) + a_sel);
            uint32_t asw1 = asw0 + 16 * 128;
            uint32_t a0[4], a1[4];
            ldsm_x4(a0[0], a0[1], a0[2], a0[3], sb + SM_A + asw0);
            ldsm_x4(a1[0], a1[1], a1[2], a1[3], sb + SM_A + asw1);

            uint32_t roff = ((uint32_t)(kk * 16) + b_row) * 128;
            #pragma unroll
            for (int pl = 0; pl < 2; ++pl) {    // ntile-pair within half
                uint32_t cu = ((uint32_t)(whalf * 2 + pl) * 2 + b_nt) * 16;
                uint32_t sw = sw128(roff + cu);
                uint32_t b0, b1, b2, b3;
                ldsm_x4t(b0, b1, b2, b3, sb + SM_B + sw);
                mma16816(acc[0][pl * 2],     a0, b0, b1);
                mma16816(acc[0][pl * 2 + 1], a0, b2, b3);
                mma16816(acc[1][pl * 2],     a1, b0, b1);
                mma16816(acc[1][pl * 2 + 1], a1, b2, b3);
            }
        }

        // ---- contiguous float4 epilogue (permuted cols) ----
        #pragma unroll
        for (int m = 0; m < 2; ++m) {
            float* oA = out + (size_t)(r0 + rA + m * 16) * 64;
            float* oB = oA + (size_t)8 * 64;
            bool okAm = m ? ok2 : ok0;
            bool okBm = m ? ok3 : ok1;
            #pragma unroll
            for (int pl = 0; pl < 2; ++pl) {
                int col = 16 * (whalf * 2 + pl) + cq;
                if (okAm) *(float4*)(oA + col) =
                    make_float4(acc[m][2 * pl][0], acc[m][2 * pl][1],
                                acc[m][2 * pl + 1][0], acc[m][2 * pl + 1][1]);
                if (okBm) *(float4*)(oB + col) =
                    make_float4(acc[m][2 * pl][2], acc[m][2 * pl][3],
                                acc[m][2 * pl + 1][2], acc[m][2 * pl + 1][3]);
            }
        }
    }
}

extern "C" void kernel_launch(void* const* d_in, const int* in_sizes, int n_in,
                              void* d_out, int out_size) {
    const float* A    = (const float*)d_in[0];
    const float* B    = (const float*)d_in[1];
    const int*   segA = (const int*)d_in[2];
    const int*   segB = (const int*)d_in[3];
    float* out = (float*)d_out;

    const int N = in_sizes[0] / 64;      // 131072
    const int S = in_sizes[3];           // 128

    preconv_B_kernel<<<S, 256>>>(B, segB);
    segmm_hmma_kernel<<<N / 64, 128>>>(A, segA, out);
}